// round 16
// baseline (speedup 1.0000x reference)
#include <cuda_runtime.h>

#define BB 16
#define NN 256
#define HH 768
#define PP 2048
#define RR 3
#define MROWS 4096

typedef unsigned long long ull;

// Scratch (__device__ globals; allocation forbidden)
__device__ float g_T1 [RR * HH * PP];          // Wh^T Wr          [3,768,2048]
__device__ float g_Mp [2 * RR * HH * HH];      // gemm2 split-K partials
__device__ float g_G  [RR * MROWS * HH];       // F @ M_r          [3,4096,768]
__device__ float g_P4 [3 * BB * RR * NN * NN]; // gemm4 split-K partials (37.7MB)
__device__ float g_wp [4 * RR * PP];           // w partials over q-chunks
__device__ float g_w  [RR * PP];
__device__ float g_zp [16 * RR * PP];          // z partials over p-chunks
__device__ float g_z  [RR * PP];
__device__ float g_uvp[16 * RR * HH];
__device__ float g_uv [2 * RR * HH];
__device__ float g_fu [RR * MROWS];
__device__ float g_fv [RR * MROWS];
__device__ float g_s  [RR];

// ---------------------------------------------------------------------------
// Packed fp32x2 helpers
// ---------------------------------------------------------------------------
__device__ __forceinline__ ull ffma2(ull a, ull b, ull c) {
    ull d;
    asm("fma.rn.f32x2 %0, %1, %2, %3;" : "=l"(d) : "l"(a), "l"(b), "l"(c));
    return d;
}
__device__ __forceinline__ ull pack2(float x) {
    ull d;
    asm("mov.b64 %0, {%1, %1};" : "=l"(d) : "f"(x));
    return d;
}
__device__ __forceinline__ float2 unpk2(ull v) {
    float2 r;
    asm("mov.b64 {%0, %1}, %2;" : "=f"(r.x), "=f"(r.y) : "l"(v));
    return r;
}
union F4U { float4 f; ull u[2]; };

// ---------------------------------------------------------------------------
// SGEMM core (proven): block tile 256(m) x 128(n), BK=16, 256 threads, 1 CTA/SM.
// ---------------------------------------------------------------------------
__device__ __forceinline__ void mm256(const float (*As)[256], const float (*Bs)[128],
                                      int ty, int tx, ull acc[8][8])
{
    const int ma0 = ty * 8, ma1 = 128 + ty * 8;
    const int na0 = tx * 4, na1 = 64 + tx * 4;
#pragma unroll
    for (int kk = 0; kk < 16; kk++) {
        F4U a0, a1, a2, a3;
        a0.f = *(const float4*)&As[kk][ma0];
        a1.f = *(const float4*)&As[kk][ma0 + 4];
        a2.f = *(const float4*)&As[kk][ma1];
        a3.f = *(const float4*)&As[kk][ma1 + 4];
        float4 b0 = *(const float4*)&Bs[kk][na0];
        float4 b1 = *(const float4*)&Bs[kk][na1];
        ull aa[8] = {a0.u[0], a0.u[1], a1.u[0], a1.u[1],
                     a2.u[0], a2.u[1], a3.u[0], a3.u[1]};
        ull bb[8] = {pack2(b0.x), pack2(b0.y), pack2(b0.z), pack2(b0.w),
                     pack2(b1.x), pack2(b1.y), pack2(b1.z), pack2(b1.w)};
#pragma unroll
        for (int mi = 0; mi < 8; mi++)
#pragma unroll
            for (int j = 0; j < 8; j++)
                acc[mi][j] = ffma2(aa[mi], bb[j], acc[mi][j]);
    }
}

template<bool AT, bool BT, bool SUMB>
__device__ __forceinline__ void gemm_core(const float* __restrict__ A, int lda,
                                          const float* __restrict__ B, int ldb,
                                          const float* __restrict__ B2,
                                          int K, int m0, int n0,
                                          int ty, int tx, ull acc[8][8])
{
    __shared__ float As[2][16][256];   // 32 KB
    __shared__ float Bs[2][16][128];   // 16 KB
    const int tid = threadIdx.x;

    const int akr = tid >> 4, acol = (tid & 15) * 16;
    const int bkr = tid >> 4, bcol = (tid & 15) * 8;
    const int btr = tid >> 1, btc = (tid & 1) * 8;

    const float* Ap = AT ? (A + (size_t)(m0 + tid) * lda)
                         : (A + (size_t)akr * lda + m0 + acol);
    const float* Bp = BT ? (B + (size_t)(n0 + btr) * ldb + btc)
                         : (B + (size_t)bkr * ldb + n0 + bcol);
    const float* Bp2 = SUMB ? (B2 + (size_t)bkr * ldb + n0 + bcol) : Bp;

    float4 av[4], bv[2];

#pragma unroll
    for (int c = 0; c < 4; c++) av[c] = *(const float4*)(Ap + c * 4);
#pragma unroll
    for (int c = 0; c < 2; c++) {
        bv[c] = *(const float4*)(Bp + c * 4);
        if (SUMB) {
            float4 b2 = *(const float4*)(Bp2 + c * 4);
            bv[c].x += b2.x; bv[c].y += b2.y; bv[c].z += b2.z; bv[c].w += b2.w;
        }
    }
    if (AT) {
#pragma unroll
        for (int c = 0; c < 4; c++) {
            As[0][c*4+0][tid] = av[c].x; As[0][c*4+1][tid] = av[c].y;
            As[0][c*4+2][tid] = av[c].z; As[0][c*4+3][tid] = av[c].w;
        }
    } else {
#pragma unroll
        for (int c = 0; c < 4; c++) *(float4*)&As[0][akr][acol + c*4] = av[c];
    }
    if (BT) {
#pragma unroll
        for (int c = 0; c < 2; c++) {
            Bs[0][btc + c*4 + 0][btr] = bv[c].x; Bs[0][btc + c*4 + 1][btr] = bv[c].y;
            Bs[0][btc + c*4 + 2][btr] = bv[c].z; Bs[0][btc + c*4 + 3][btr] = bv[c].w;
        }
    } else {
#pragma unroll
        for (int c = 0; c < 2; c++) *(float4*)&Bs[0][bkr][bcol + c*4] = bv[c];
    }
    __syncthreads();

    int buf = 0;
    for (int k0 = 16; k0 < K; k0 += 16) {
#pragma unroll
        for (int c = 0; c < 4; c++)
            av[c] = AT ? *(const float4*)(Ap + k0 + c * 4)
                       : *(const float4*)(Ap + (size_t)k0 * lda + c * 4);
#pragma unroll
        for (int c = 0; c < 2; c++) {
            bv[c] = BT ? *(const float4*)(Bp + k0 + c * 4)
                       : *(const float4*)(Bp + (size_t)k0 * ldb + c * 4);
            if (SUMB) {
                float4 b2 = *(const float4*)(Bp2 + (size_t)k0 * ldb + c * 4);
                bv[c].x += b2.x; bv[c].y += b2.y; bv[c].z += b2.z; bv[c].w += b2.w;
            }
        }

        mm256(As[buf], Bs[buf], ty, tx, acc);

        const int nb = buf ^ 1;
        if (AT) {
#pragma unroll
            for (int c = 0; c < 4; c++) {
                As[nb][c*4+0][tid] = av[c].x; As[nb][c*4+1][tid] = av[c].y;
                As[nb][c*4+2][tid] = av[c].z; As[nb][c*4+3][tid] = av[c].w;
            }
        } else {
#pragma unroll
            for (int c = 0; c < 4; c++) *(float4*)&As[nb][akr][acol + c*4] = av[c];
        }
        if (BT) {
#pragma unroll
            for (int c = 0; c < 2; c++) {
                Bs[nb][btc + c*4 + 0][btr] = bv[c].x; Bs[nb][btc + c*4 + 1][btr] = bv[c].y;
                Bs[nb][btc + c*4 + 2][btr] = bv[c].z; Bs[nb][btc + c*4 + 3][btr] = bv[c].w;
            }
        } else {
#pragma unroll
            for (int c = 0; c < 2; c++) *(float4*)&Bs[nb][bkr][bcol + c*4] = bv[c];
        }
        __syncthreads();
        buf = nb;
    }
    mm256(As[buf], Bs[buf], ty, tx, acc);
}

#define MICRO_IDX                                   \
    const int tid = threadIdx.x;                    \
    const int tx = tid & 15, ty = tid >> 4;         \
    ull acc[8][8];                                  \
    _Pragma("unroll") for (int i = 0; i < 8; i++)   \
    _Pragma("unroll") for (int j = 0; j < 8; j++) acc[i][j] = 0ull;

__device__ __forceinline__ int mrow_of(int mi, int ty) {
    return (mi < 4) ? (ty * 8 + 2 * mi) : (128 + ty * 8 + 2 * (mi - 4));
}

__device__ __forceinline__ void store_plain(float* C, int ldc, int m0, int n0,
                                            int ty, int tx, const ull acc[8][8])
{
    const int na0 = n0 + tx * 4, na1 = n0 + 64 + tx * 4;
#pragma unroll
    for (int mi = 0; mi < 8; mi++) {
        const int row = m0 + mrow_of(mi, ty);
        float2 p[8];
#pragma unroll
        for (int j = 0; j < 8; j++) p[j] = unpk2(acc[mi][j]);
        float* r0 = C + (size_t)row * ldc;
        float* r1 = C + (size_t)(row + 1) * ldc;
        *(float4*)(r0 + na0) = make_float4(p[0].x, p[1].x, p[2].x, p[3].x);
        *(float4*)(r0 + na1) = make_float4(p[4].x, p[5].x, p[6].x, p[7].x);
        *(float4*)(r1 + na0) = make_float4(p[0].y, p[1].y, p[2].y, p[3].y);
        *(float4*)(r1 + na1) = make_float4(p[4].y, p[5].y, p[6].y, p[7].y);
    }
}

// ---------------------------------------------------------------------------
// gemm1: T1_r[h,q] = sum_p Wh[p,h] * Wr[r,p,q]   M=768 N=2048 K=2048
// ---------------------------------------------------------------------------
__global__ __launch_bounds__(256, 1) void gemm1_kernel(
    const float* __restrict__ hW, const float* __restrict__ bilW)
{
    const int r  = blockIdx.z;
    const int m0 = blockIdx.y * 256;
    const int n0 = blockIdx.x * 128;
    MICRO_IDX;
    gemm_core<false, false, false>(hW, HH, bilW + (size_t)r * PP * PP, PP, nullptr,
                                   PP, m0, n0, ty, tx, acc);
    store_plain(g_T1 + (size_t)r * HH * PP, PP, m0, n0, ty, tx, acc);
}

// ---------------------------------------------------------------------------
// gemm2 (split-K=2): Mp[kh][r][h,h2] = sum_{q half} T1_r[h,q] * Wt[q,h2]
// ---------------------------------------------------------------------------
__global__ __launch_bounds__(256, 1) void gemm2_kernel(const float* __restrict__ tW)
{
    const int z  = blockIdx.z;
    const int r  = z >> 1;
    const int kh = z & 1;
    const int m0 = blockIdx.y * 256;
    const int n0 = blockIdx.x * 128;
    MICRO_IDX;
    gemm_core<true, false, false>(g_T1 + (size_t)r * HH * PP + kh * 1024, PP,
                                  tW + (size_t)kh * 1024 * HH, HH, nullptr,
                                  1024, m0, n0, ty, tx, acc);
    store_plain(g_Mp + ((size_t)kh * RR + r) * HH * HH, HH, m0, n0, ty, tx, acc);
}

// ---------------------------------------------------------------------------
// gemm3: G_r[n,h2] = sum_h F[n,h] * (Mp0_r + Mp1_r)[h,h2]   M=4096 N=768 K=768
// ---------------------------------------------------------------------------
__global__ __launch_bounds__(256, 1) void gemm3_kernel(const float* __restrict__ F)
{
    const int r  = blockIdx.z;
    const int m0 = blockIdx.y * 256;
    const int n0 = blockIdx.x * 128;
    MICRO_IDX;
    gemm_core<true, false, true>(F, HH,
                                 g_Mp + (size_t)r * HH * HH, HH,
                                 g_Mp + ((size_t)RR + r) * HH * HH,
                                 HH, m0, n0, ty, tx, acc);
    store_plain(g_G + (size_t)r * MROWS * HH, HH, m0, n0, ty, tx, acc);
}

// ---------------------------------------------------------------------------
// gemm4 (split-K=3): P4[kh][z][n,m], K=256 per block.  288 blocks = 2 waves.
// ---------------------------------------------------------------------------
__global__ __launch_bounds__(256, 1) void gemm4_kernel(const float* __restrict__ F)
{
    const int z  = blockIdx.z;
    const int b  = z / RR;
    const int r  = z % RR;
    const int kh = blockIdx.y;
    const int n0 = blockIdx.x * 128;
    MICRO_IDX;
    const float* A  = g_G + ((size_t)r * MROWS + (size_t)b * NN) * HH + kh * 256;
    const float* Bm = F + (size_t)b * NN * HH + kh * 256;
    gemm_core<true, true, false>(A, HH, Bm, HH, nullptr, 256, 0, n0, ty, tx, acc);
    store_plain(g_P4 + ((size_t)kh * (BB * RR) + z) * NN * NN, NN, 0, n0, ty, tx, acc);
}

// reduce4: out[b,n,m,r] = sum_kh P4 + fu + fv + s
__global__ void reduce4_kernel(float* __restrict__ out)
{
    const size_t i = (size_t)blockIdx.x * 256 + threadIdx.x;
    const int z    = (int)(i >> 16);
    const int rem  = (int)(i & 65535);
    const int nrow = rem >> 8, mcol = rem & 255;
    const int b = z / RR, r = z % RR;
    const size_t plane = (size_t)(BB * RR) * NN * NN;
    float a = g_P4[i] + g_P4[plane + i] + g_P4[2 * plane + i];
    a += g_fu[r * MROWS + b * NN + nrow] + g_fv[r * MROWS + b * NN + mcol] + g_s[r];
    out[(((size_t)b * NN + nrow) * NN + mcol) * RR + r] = a;
}

// ---------------------------------------------------------------------------
// Vector stage — single-pass fused w+z over bil_W (reads 50MB ONCE)
// grid (4, 48): x = q-chunk (512 cols), y = r*16 + p-chunk (128 rows)
// ---------------------------------------------------------------------------
__global__ void vec_wz_fused(const float* __restrict__ bilW,
                             const float* __restrict__ bt,
                             const float* __restrict__ bh)
{
    __shared__ float wsh[8][128];
    const int qc = blockIdx.x;
    const int r  = blockIdx.y >> 4, pc = blockIdx.y & 15;
    const int tid = threadIdx.x, warp = tid >> 5, lane = tid & 31;
    const int q0 = qc * 512 + tid * 2;
    const float bt0 = __ldg(&bt[q0]), bt1 = __ldg(&bt[q0 + 1]);
    const float* base = bilW + ((size_t)r * PP + pc * 128) * PP + q0;
    float z0 = 0.f, z1 = 0.f;
#pragma unroll 4
    for (int p = 0; p < 128; p++) {
        const float2 v = *(const float2*)(base + (size_t)p * PP);
        const float bhp = __ldg(&bh[pc * 128 + p]);
        z0 += bhp * v.x; z1 += bhp * v.y;
        float ws = v.x * bt0 + v.y * bt1;
#pragma unroll
        for (int o = 16; o; o >>= 1) ws += __shfl_down_sync(0xFFFFFFFFu, ws, o);
        if (lane == 0) wsh[warp][p] = ws;
    }
    __syncthreads();
    *(float2*)&g_zp[((size_t)pc * RR + r) * PP + q0] = make_float2(z0, z1);
    if (tid < 128) {
        float a = 0.f;
#pragma unroll
        for (int w8 = 0; w8 < 8; w8++) a += wsh[w8][tid];
        g_wp[((size_t)qc * RR + r) * PP + pc * 128 + tid] = a;
    }
}

// combined reduce: blocks [0,24) z; [24,48) w; [48,51) s (from wp, fixed order)
__global__ void reduce_wzs_kernel(const float* __restrict__ bh,
                                  const float* __restrict__ bilb)
{
    const int b = blockIdx.x;
    if (b < 24) {
        const int o = b * 256 + threadIdx.x;
        float a = 0.f;
#pragma unroll
        for (int sp = 0; sp < 16; sp++) a += g_zp[(size_t)sp * RR * PP + o];
        g_z[o] = a;
    } else if (b < 48) {
        const int o = (b - 24) * 256 + threadIdx.x;
        const size_t pl = (size_t)RR * PP;
        g_w[o] = g_wp[o] + g_wp[pl + o] + g_wp[2 * pl + o] + g_wp[3 * pl + o];
    } else {
        const int r = b - 48;
        const size_t pl = (size_t)RR * PP;
        __shared__ float red[256];
        float a = 0.f;
        for (int p = threadIdx.x; p < PP; p += 256) {
            const size_t o = (size_t)r * PP + p;
            const float wv = g_wp[o] + g_wp[pl + o] + g_wp[2 * pl + o] + g_wp[3 * pl + o];
            a += bh[p] * wv;
        }
        red[threadIdx.x] = a;
        __syncthreads();
        for (int o = 128; o; o >>= 1) {
            if (threadIdx.x < o) red[threadIdx.x] += red[threadIdx.x + o];
            __syncthreads();
        }
        if (threadIdx.x == 0) g_s[r] = red[0] + bilb[r];
    }
}

__global__ void vec_uv_part(const float* __restrict__ hW, const float* __restrict__ tW)
{
    const int sel = blockIdx.z >> 3, sp = blockIdx.z & 7;
    const int r = blockIdx.y;
    const int h = blockIdx.x * 256 + threadIdx.x;
    const float* Wm  = sel ? tW : hW;
    const float* vin = (sel ? g_z : g_w) + (size_t)r * PP + sp * 256;
    const float* base = Wm + (size_t)sp * 256 * HH + h;
    float a = 0.f;
#pragma unroll 4
    for (int p = 0; p < 256; p++) a += base[(size_t)p * HH] * __ldg(&vin[p]);
    g_uvp[((size_t)(sel * 8 + sp) * RR + r) * HH + h] = a;
}

__global__ void reduce_uv() {
    const int o = blockIdx.x * 256 + threadIdx.x;
    const int sel = o / (RR * HH);
    const int rem = o % (RR * HH);
    float a = 0.f;
#pragma unroll
    for (int sp = 0; sp < 8; sp++) a += g_uvp[((size_t)(sel * 8 + sp) * RR * HH) + rem];
    g_uv[o] = a;
}

__global__ void vec_fufv_kernel(const float* __restrict__ F)
{
    const int sel = blockIdx.z;
    const int r = blockIdx.y;
    const int warp = threadIdx.x >> 5, lane = threadIdx.x & 31;
    const int n = blockIdx.x * 8 + warp;
    const float* f  = F + (size_t)n * HH;
    const float* vv = g_uv + ((size_t)sel * RR + r) * HH;
    float a = 0.f;
    for (int h = lane; h < HH; h += 32) a += f[h] * __ldg(&vv[h]);
#pragma unroll
    for (int o = 16; o; o >>= 1) a += __shfl_down_sync(0xFFFFFFFFu, a, o);
    if (lane == 0) (sel ? g_fv : g_fu)[r * MROWS + n] = a;
}

// ---------------------------------------------------------------------------
// Launch
// ---------------------------------------------------------------------------
extern "C" void kernel_launch(void* const* d_in, const int* in_sizes, int n_in,
                              void* d_out, int out_size)
{
    const float* features = (const float*)d_in[0];
    const float* head_W   = (const float*)d_in[1];
    const float* head_b   = (const float*)d_in[2];
    const float* tail_W   = (const float*)d_in[3];
    const float* tail_b   = (const float*)d_in[4];
    const float* bil_W    = (const float*)d_in[5];
    const float* bil_b    = (const float*)d_in[6];
    float* out = (float*)d_out;

    dim3 blk(256);

    // vector/bias path (single-pass w+z)
    vec_wz_fused     <<<dim3(4, 48), blk>>>(bil_W, tail_b, head_b);
    reduce_wzs_kernel<<<dim3(51), blk>>>(head_b, bil_b);
    vec_uv_part      <<<dim3(HH / 256, RR, 16), blk>>>(head_W, tail_W);
    reduce_uv        <<<dim3(2 * RR * HH / 256), blk>>>();
    vec_fufv_kernel  <<<dim3(MROWS / 8, RR, 2), blk>>>(features);

    // factored GEMM chain
    gemm1_kernel  <<<dim3(PP / 128, HH / 256, RR), blk>>>(head_W, bil_W);
    gemm2_kernel  <<<dim3(HH / 128, HH / 256, RR * 2), blk>>>(tail_W);
    gemm3_kernel  <<<dim3(HH / 128, MROWS / 256, RR), blk>>>(features);
    gemm4_kernel  <<<dim3(NN / 128, 3, BB * RR), blk>>>(features);
    reduce4_kernel<<<dim3(BB * RR * NN * NN / 256), blk>>>(out);
}

// round 17
// speedup vs baseline: 1.0503x; 1.0503x over previous
#include <cuda_runtime.h>

#define BB 16
#define NN 256
#define HH 768
#define PP 2048
#define RR 3
#define MROWS 4096

typedef unsigned long long ull;

// Scratch (__device__ globals; allocation forbidden)
__device__ float g_T1 [RR * HH * PP];          // Wh^T Wr          [3,768,2048]
__device__ float g_Mp [2 * RR * HH * HH];      // gemm2 split-K partials
__device__ float g_G  [RR * MROWS * HH];       // F @ M_r          [3,4096,768]
__device__ float g_P4 [3 * BB * RR * NN * NN]; // gemm4 split-K partials
__device__ float g_w  [RR * PP];
__device__ float g_zp [16 * RR * PP];
__device__ float g_z  [RR * PP];
__device__ float g_uvp[16 * RR * HH];
__device__ float g_uv [2 * RR * HH];
__device__ float g_fu [RR * MROWS];
__device__ float g_fv [RR * MROWS];
__device__ float g_s  [RR];

// ---------------------------------------------------------------------------
// Packed fp32x2 helpers
// ---------------------------------------------------------------------------
__device__ __forceinline__ ull ffma2(ull a, ull b, ull c) {
    ull d;
    asm("fma.rn.f32x2 %0, %1, %2, %3;" : "=l"(d) : "l"(a), "l"(b), "l"(c));
    return d;
}
__device__ __forceinline__ ull pack2(float x) {
    ull d;
    asm("mov.b64 %0, {%1, %1};" : "=l"(d) : "f"(x));
    return d;
}
__device__ __forceinline__ float2 unpk2(ull v) {
    float2 r;
    asm("mov.b64 {%0, %1}, %2;" : "=f"(r.x), "=f"(r.y) : "l"(v));
    return r;
}
union F4U { float4 f; ull u[2]; };

// ---------------------------------------------------------------------------
// SGEMM core (proven): block tile 256(m) x 128(n), BK=16, 256 threads, 1 CTA/SM.
// ---------------------------------------------------------------------------
__device__ __forceinline__ void mm256(const float (*As)[256], const float (*Bs)[128],
                                      int ty, int tx, ull acc[8][8])
{
    const int ma0 = ty * 8, ma1 = 128 + ty * 8;
    const int na0 = tx * 4, na1 = 64 + tx * 4;
#pragma unroll
    for (int kk = 0; kk < 16; kk++) {
        F4U a0, a1, a2, a3;
        a0.f = *(const float4*)&As[kk][ma0];
        a1.f = *(const float4*)&As[kk][ma0 + 4];
        a2.f = *(const float4*)&As[kk][ma1];
        a3.f = *(const float4*)&As[kk][ma1 + 4];
        float4 b0 = *(const float4*)&Bs[kk][na0];
        float4 b1 = *(const float4*)&Bs[kk][na1];
        ull aa[8] = {a0.u[0], a0.u[1], a1.u[0], a1.u[1],
                     a2.u[0], a2.u[1], a3.u[0], a3.u[1]};
        ull bb[8] = {pack2(b0.x), pack2(b0.y), pack2(b0.z), pack2(b0.w),
                     pack2(b1.x), pack2(b1.y), pack2(b1.z), pack2(b1.w)};
#pragma unroll
        for (int mi = 0; mi < 8; mi++)
#pragma unroll
            for (int j = 0; j < 8; j++)
                acc[mi][j] = ffma2(aa[mi], bb[j], acc[mi][j]);
    }
}

template<bool AT, bool BT, bool SUMB>
__device__ __forceinline__ void gemm_core(const float* __restrict__ A, int lda,
                                          const float* __restrict__ B, int ldb,
                                          const float* __restrict__ B2,
                                          int K, int m0, int n0,
                                          int ty, int tx, ull acc[8][8])
{
    __shared__ float As[2][16][256];   // 32 KB
    __shared__ float Bs[2][16][128];   // 16 KB
    const int tid = threadIdx.x;

    const int akr = tid >> 4, acol = (tid & 15) * 16;
    const int bkr = tid >> 4, bcol = (tid & 15) * 8;
    const int btr = tid >> 1, btc = (tid & 1) * 8;

    const float* Ap = AT ? (A + (size_t)(m0 + tid) * lda)
                         : (A + (size_t)akr * lda + m0 + acol);
    const float* Bp = BT ? (B + (size_t)(n0 + btr) * ldb + btc)
                         : (B + (size_t)bkr * ldb + n0 + bcol);
    const float* Bp2 = SUMB ? (B2 + (size_t)bkr * ldb + n0 + bcol) : Bp;

    float4 av[4], bv[2];

#pragma unroll
    for (int c = 0; c < 4; c++) av[c] = *(const float4*)(Ap + c * 4);
#pragma unroll
    for (int c = 0; c < 2; c++) {
        bv[c] = *(const float4*)(Bp + c * 4);
        if (SUMB) {
            float4 b2 = *(const float4*)(Bp2 + c * 4);
            bv[c].x += b2.x; bv[c].y += b2.y; bv[c].z += b2.z; bv[c].w += b2.w;
        }
    }
    if (AT) {
#pragma unroll
        for (int c = 0; c < 4; c++) {
            As[0][c*4+0][tid] = av[c].x; As[0][c*4+1][tid] = av[c].y;
            As[0][c*4+2][tid] = av[c].z; As[0][c*4+3][tid] = av[c].w;
        }
    } else {
#pragma unroll
        for (int c = 0; c < 4; c++) *(float4*)&As[0][akr][acol + c*4] = av[c];
    }
    if (BT) {
#pragma unroll
        for (int c = 0; c < 2; c++) {
            Bs[0][btc + c*4 + 0][btr] = bv[c].x; Bs[0][btc + c*4 + 1][btr] = bv[c].y;
            Bs[0][btc + c*4 + 2][btr] = bv[c].z; Bs[0][btc + c*4 + 3][btr] = bv[c].w;
        }
    } else {
#pragma unroll
        for (int c = 0; c < 2; c++) *(float4*)&Bs[0][bkr][bcol + c*4] = bv[c];
    }
    __syncthreads();

    int buf = 0;
    for (int k0 = 16; k0 < K; k0 += 16) {
#pragma unroll
        for (int c = 0; c < 4; c++)
            av[c] = AT ? *(const float4*)(Ap + k0 + c * 4)
                       : *(const float4*)(Ap + (size_t)k0 * lda + c * 4);
#pragma unroll
        for (int c = 0; c < 2; c++) {
            bv[c] = BT ? *(const float4*)(Bp + k0 + c * 4)
                       : *(const float4*)(Bp + (size_t)k0 * ldb + c * 4);
            if (SUMB) {
                float4 b2 = *(const float4*)(Bp2 + (size_t)k0 * ldb + c * 4);
                bv[c].x += b2.x; bv[c].y += b2.y; bv[c].z += b2.z; bv[c].w += b2.w;
            }
        }

        mm256(As[buf], Bs[buf], ty, tx, acc);

        const int nb = buf ^ 1;
        if (AT) {
#pragma unroll
            for (int c = 0; c < 4; c++) {
                As[nb][c*4+0][tid] = av[c].x; As[nb][c*4+1][tid] = av[c].y;
                As[nb][c*4+2][tid] = av[c].z; As[nb][c*4+3][tid] = av[c].w;
            }
        } else {
#pragma unroll
            for (int c = 0; c < 4; c++) *(float4*)&As[nb][akr][acol + c*4] = av[c];
        }
        if (BT) {
#pragma unroll
            for (int c = 0; c < 2; c++) {
                Bs[nb][btc + c*4 + 0][btr] = bv[c].x; Bs[nb][btc + c*4 + 1][btr] = bv[c].y;
                Bs[nb][btc + c*4 + 2][btr] = bv[c].z; Bs[nb][btc + c*4 + 3][btr] = bv[c].w;
            }
        } else {
#pragma unroll
            for (int c = 0; c < 2; c++) *(float4*)&Bs[nb][bkr][bcol + c*4] = bv[c];
        }
        __syncthreads();
        buf = nb;
    }
    mm256(As[buf], Bs[buf], ty, tx, acc);
}

#define MICRO_IDX                                   \
    const int tid = threadIdx.x;                    \
    const int tx = tid & 15, ty = tid >> 4;         \
    ull acc[8][8];                                  \
    _Pragma("unroll") for (int i = 0; i < 8; i++)   \
    _Pragma("unroll") for (int j = 0; j < 8; j++) acc[i][j] = 0ull;

__device__ __forceinline__ int mrow_of(int mi, int ty) {
    return (mi < 4) ? (ty * 8 + 2 * mi) : (128 + ty * 8 + 2 * (mi - 4));
}

__device__ __forceinline__ void store_plain(float* C, int ldc, int m0, int n0,
                                            int ty, int tx, const ull acc[8][8])
{
    const int na0 = n0 + tx * 4, na1 = n0 + 64 + tx * 4;
#pragma unroll
    for (int mi = 0; mi < 8; mi++) {
        const int row = m0 + mrow_of(mi, ty);
        float2 p[8];
#pragma unroll
        for (int j = 0; j < 8; j++) p[j] = unpk2(acc[mi][j]);
        float* r0 = C + (size_t)row * ldc;
        float* r1 = C + (size_t)(row + 1) * ldc;
        *(float4*)(r0 + na0) = make_float4(p[0].x, p[1].x, p[2].x, p[3].x);
        *(float4*)(r0 + na1) = make_float4(p[4].x, p[5].x, p[6].x, p[7].x);
        *(float4*)(r1 + na0) = make_float4(p[0].y, p[1].y, p[2].y, p[3].y);
        *(float4*)(r1 + na1) = make_float4(p[4].y, p[5].y, p[6].y, p[7].y);
    }
}

// ---------------------------------------------------------------------------
// vec_wz (standalone, round-15 proven): w full dots + zp partials
// ---------------------------------------------------------------------------
__global__ void vec_wz_kernel(const float* __restrict__ bilW,
                              const float* __restrict__ bt,
                              const float* __restrict__ bh)
{
    int bid = blockIdx.x;
    if (bid < 768) {
        const int r = bid / 256, px = bid % 256;
        const int warp = threadIdx.x >> 5, lane = threadIdx.x & 31;
        const int p = px * 8 + warp;
        const float* row = bilW + ((size_t)r * PP + p) * PP;
        float a = 0.f;
        for (int q = lane; q < PP; q += 32) a += row[q] * __ldg(&bt[q]);
#pragma unroll
        for (int o = 16; o; o >>= 1) a += __shfl_down_sync(0xFFFFFFFFu, a, o);
        if (lane == 0) g_w[r * PP + p] = a;
    } else {
        bid -= 768;
        const int x = bid & 7, r = (bid >> 3) % 3, sp = bid / 24;
        const int q = x * 256 + threadIdx.x;
        const float* base = bilW + (size_t)r * PP * PP + (size_t)sp * 128 * PP + q;
        float a = 0.f;
#pragma unroll 4
        for (int p = 0; p < 128; p++) a += __ldg(&bh[sp * 128 + p]) * base[(size_t)p * PP];
        g_zp[((size_t)sp * RR + r) * PP + q] = a;
    }
}

// ---------------------------------------------------------------------------
// gemm1 (+4 extras: z-reduce + s, all shuffle/no-smem):
// T1_r[h,q] = sum_p Wh[p,h] * Wr[r,p,q]   M=768 N=2048 K=2048.  grid 148.
// ---------------------------------------------------------------------------
__global__ __launch_bounds__(256, 1) void gemm1_kernel(
    const float* __restrict__ hW, const float* __restrict__ bilW,
    const float* __restrict__ bh, const float* __restrict__ bilb)
{
    const int t = blockIdx.x;
    if (t >= 144) {
        const int vid = t - 144;
        const int warp = threadIdx.x >> 5, lane = threadIdx.x & 31;
        for (int u = vid; u < 27; u += 4) {
            if (u < 24) {
                const int o = u * 256 + threadIdx.x;
                float a = 0.f;
#pragma unroll
                for (int sp = 0; sp < 16; sp++) a += g_zp[(size_t)sp * RR * PP + o];
                g_z[o] = a;
            } else if (warp == 0) {
                const int r = u - 24;
                float a = 0.f;
                for (int p = lane; p < PP; p += 32) a += __ldg(&bh[p]) * g_w[r * PP + p];
#pragma unroll
                for (int o = 16; o; o >>= 1) a += __shfl_down_sync(0xFFFFFFFFu, a, o);
                if (lane == 0) g_s[r] = a + bilb[r];
            }
        }
        return;
    }
    const int n0 = (t & 15) * 128;
    const int m0 = ((t >> 4) % 3) * 256;
    const int r  = t / 48;
    MICRO_IDX;
    gemm_core<false, false, false>(hW, HH, bilW + (size_t)r * PP * PP, PP, nullptr,
                                   PP, m0, n0, ty, tx, acc);
    store_plain(g_T1 + (size_t)r * HH * PP, PP, m0, n0, ty, tx, acc);
}

// ---------------------------------------------------------------------------
// gemm2 (+40 extras: uv partials, 144 units round-robin):
// Mp[kh][r] = T1_r[:,half] Wt[half,:]  (split-K=2).  grid 148.
// ---------------------------------------------------------------------------
__global__ __launch_bounds__(256, 1) void gemm2_kernel(
    const float* __restrict__ tW, const float* __restrict__ hW)
{
    const int t = blockIdx.x;
    if (t >= 108) {
        const int vid = t - 108;
        for (int u = vid; u < 144; u += 40) {
            const int hc = u % 3, r = (u / 3) % 3, zz = u / 9;
            const int sel = zz >> 3, sp = zz & 7;
            const int h = hc * 256 + threadIdx.x;
            const float* Wm  = sel ? tW : hW;
            const float* vin = (sel ? g_z : g_w) + (size_t)r * PP + sp * 256;
            const float* base = Wm + (size_t)sp * 256 * HH + h;
            float a = 0.f;
#pragma unroll 4
            for (int p = 0; p < 256; p++) a += base[(size_t)p * HH] * __ldg(&vin[p]);
            g_uvp[((size_t)(sel * 8 + sp) * RR + r) * HH + h] = a;
        }
        return;
    }
    const int n0 = (t % 6) * 128;
    const int m0 = ((t / 6) % 3) * 256;
    const int z  = t / 18;
    const int r  = z >> 1, kh = z & 1;
    MICRO_IDX;
    gemm_core<true, false, false>(g_T1 + (size_t)r * HH * PP + kh * 1024, PP,
                                  tW + (size_t)kh * 1024 * HH, HH, nullptr,
                                  1024, m0, n0, ty, tx, acc);
    store_plain(g_Mp + ((size_t)kh * RR + r) * HH * HH, HH, m0, n0, ty, tx, acc);
}

__global__ void reduce_uv() {
    const int o = blockIdx.x * 256 + threadIdx.x;
    const int sel = o / (RR * HH);
    const int rem = o % (RR * HH);
    float a = 0.f;
#pragma unroll
    for (int sp = 0; sp < 8; sp++) a += g_uvp[((size_t)(sel * 8 + sp) * RR * HH) + rem];
    g_uv[o] = a;
}

__global__ void vec_fufv_kernel(const float* __restrict__ F)
{
    const int sel = blockIdx.z;
    const int r = blockIdx.y;
    const int warp = threadIdx.x >> 5, lane = threadIdx.x & 31;
    const int n = blockIdx.x * 8 + warp;
    const float* f  = F + (size_t)n * HH;
    const float* vv = g_uv + ((size_t)sel * RR + r) * HH;
    float a = 0.f;
    for (int h = lane; h < HH; h += 32) a += f[h] * __ldg(&vv[h]);
#pragma unroll
    for (int o = 16; o; o >>= 1) a += __shfl_down_sync(0xFFFFFFFFu, a, o);
    if (lane == 0) (sel ? g_fv : g_fu)[r * MROWS + n] = a;
}

// ---------------------------------------------------------------------------
// gemm3: G_r[n,h2] = sum_h F[n,h] * (Mp0_r + Mp1_r)[h,h2]   M=4096 N=768 K=768
// ---------------------------------------------------------------------------
__global__ __launch_bounds__(256, 1) void gemm3_kernel(const float* __restrict__ F)
{
    const int r  = blockIdx.z;
    const int m0 = blockIdx.y * 256;
    const int n0 = blockIdx.x * 128;
    MICRO_IDX;
    gemm_core<true, false, true>(F, HH,
                                 g_Mp + (size_t)r * HH * HH, HH,
                                 g_Mp + ((size_t)RR + r) * HH * HH,
                                 HH, m0, n0, ty, tx, acc);
    store_plain(g_G + (size_t)r * MROWS * HH, HH, m0, n0, ty, tx, acc);
}

// ---------------------------------------------------------------------------
// gemm4 (split-K=3): P4[kh][z][n,m], K=256 per block.  288 blocks = 2 waves.
// ---------------------------------------------------------------------------
__global__ __launch_bounds__(256, 1) void gemm4_kernel(const float* __restrict__ F)
{
    const int z  = blockIdx.z;
    const int b  = z / RR;
    const int r  = z % RR;
    const int kh = blockIdx.y;
    const int n0 = blockIdx.x * 128;
    MICRO_IDX;
    const float* A  = g_G + ((size_t)r * MROWS + (size_t)b * NN) * HH + kh * 256;
    const float* Bm = F + (size_t)b * NN * HH + kh * 256;
    gemm_core<true, true, false>(A, HH, Bm, HH, nullptr, 256, 0, n0, ty, tx, acc);
    store_plain(g_P4 + ((size_t)kh * (BB * RR) + z) * NN * NN, NN, 0, n0, ty, tx, acc);
}

// reduce4: out[b,n,m,r] = sum_kh P4 + fu + fv + s
__global__ void reduce4_kernel(float* __restrict__ out)
{
    const size_t i = (size_t)blockIdx.x * 256 + threadIdx.x;
    const int z    = (int)(i >> 16);
    const int rem  = (int)(i & 65535);
    const int nrow = rem >> 8, mcol = rem & 255;
    const int b = z / RR, r = z % RR;
    const size_t plane = (size_t)(BB * RR) * NN * NN;
    float a = g_P4[i] + g_P4[plane + i] + g_P4[2 * plane + i];
    a += g_fu[r * MROWS + b * NN + nrow] + g_fv[r * MROWS + b * NN + mcol] + g_s[r];
    out[(((size_t)b * NN + nrow) * NN + mcol) * RR + r] = a;
}

// ---------------------------------------------------------------------------
// Launch — 8 kernels
// ---------------------------------------------------------------------------
extern "C" void kernel_launch(void* const* d_in, const int* in_sizes, int n_in,
                              void* d_out, int out_size)
{
    const float* features = (const float*)d_in[0];
    const float* head_W   = (const float*)d_in[1];
    const float* head_b   = (const float*)d_in[2];
    const float* tail_W   = (const float*)d_in[3];
    const float* tail_b   = (const float*)d_in[4];
    const float* bil_W    = (const float*)d_in[5];
    const float* bil_b    = (const float*)d_in[6];
    float* out = (float*)d_out;

    dim3 blk(256);

    vec_wz_kernel  <<<dim3(1152), blk>>>(bil_W, tail_b, head_b);
    gemm1_kernel   <<<dim3(148), blk>>>(head_W, bil_W, head_b, bil_b);
    gemm2_kernel   <<<dim3(148), blk>>>(tail_W, head_W);
    reduce_uv      <<<dim3(2 * RR * HH / 256), blk>>>();
    vec_fufv_kernel<<<dim3(MROWS / 8, RR, 2), blk>>>(features);
    gemm3_kernel   <<<dim3(HH / 128, MROWS / 256, RR), blk>>>(features);
    gemm4_kernel   <<<dim3(NN / 128, 3, BB * RR), blk>>>(features);
    reduce4_kernel <<<dim3(BB * RR * NN * NN / 256), blk>>>(out);
}